// round 2
// baseline (speedup 1.0000x reference)
#include <cuda_runtime.h>
#include <math.h>

#define H1 256
#define W1 320
#define H2 128
#define W2 160
#define HOUT 512
#define WOUT 640
#define DEPTH 48
#define HW1 (H1*W1)
#define HW2 (H2*W2)
#define HWO (HOUT*WOUT)

typedef unsigned long long u64;

// ---------------- scratch state (device globals; no allocation allowed) ----
__device__ float g_s1 [8  * HW1];
__device__ float g_s2 [16 * HW2];
__device__ float g_c1 [8  * HW1];
__device__ float g_u1 [8  * HW1];
__device__ float g_rh1[8  * HW1];
__device__ float g_c2 [16 * HW2];
__device__ float g_u2 [16 * HW2];
__device__ float g_rh2[16 * HW2];
__device__ float g_up [8  * HW1];

// ---------------- packed f32x2 helpers -------------------------------------
__device__ __forceinline__ u64 pack2(float lo, float hi) {
    u64 r; asm("mov.b64 %0, {%1, %2};" : "=l"(r) : "f"(lo), "f"(hi)); return r;
}
__device__ __forceinline__ void unpack2(u64 v, float& lo, float& hi) {
    asm("mov.b64 {%0, %1}, %2;" : "=f"(lo), "=f"(hi) : "l"(v));
}
__device__ __forceinline__ void ffma2(u64& d, u64 a, u64 b) {
    asm("fma.rn.f32x2 %0, %1, %2, %0;" : "+l"(d) : "l"(a), "l"(b));
}

__device__ __forceinline__ float sigf(float x) {
    return __fdividef(1.0f, 1.0f + __expf(-x));
}
__device__ __forceinline__ float tanh_fast(float x) {
    return __fdividef(2.0f, 1.0f + __expf(-2.0f * x)) - 1.0f;
}

// ---------------- weight loaders -------------------------------------------
// conv weight global layout: w[co_total][cin_tot][3][3]
// shared layout: ws[(ci*9+k)*COB + co]  (co contiguous -> LDS.64 gives co pair)
template<int CIN_TOT, int COB>
__device__ __forceinline__ void load_w_conv(float* ws, const float* __restrict__ w, int co_base) {
    const int n = CIN_TOT * 9 * COB;
    for (int i = threadIdx.x; i < n; i += blockDim.x) {
        int co   = i % COB;
        int rest = i / COB;
        ws[i] = w[(co_base + co) * (CIN_TOT * 9) + rest];
    }
}
// deconv weight global layout: w[cin][cout_total][3][3]
template<int CIN, int COB, int COUT_TOT>
__device__ __forceinline__ void load_w_deconv(float* ws, const float* __restrict__ w, int co_base) {
    const int n = CIN * 9 * COB;
    for (int i = threadIdx.x; i < n; i += blockDim.x) {
        int co   = i % COB;
        int rest = i / COB;
        int ci   = rest / 9;
        int k    = rest - ci * 9;
        ws[i] = w[(ci * COUT_TOT + co_base + co) * 9 + k];
    }
}

// ---------------- P4 conv core ---------------------------------------------
// acc[cp][p] packs output channels (2cp, 2cp+1) for pixel x0+p.
template<int CA, int CB, int COB, int STRIDE, int CIUNROLL>
__device__ __forceinline__ void conv_p4(u64 (&acc)[COB/2][4], const float* ws,
                                        const float* __restrict__ inA, int csA,
                                        const float* __restrict__ inB, int csB,
                                        int y, int x0, int Hin, int Win) {
    constexpr int NIN = (STRIDE == 1) ? 6 : 9;
    const int bx = x0 * STRIDE - 1;
#pragma unroll CIUNROLL
    for (int ci = 0; ci < CA + CB; ci++) {
        const float* src = (ci < CA) ? (inA + ci * csA) : (inB + (ci - CA) * csB);
#pragma unroll
        for (int ky = 0; ky < 3; ky++) {
            int iy = y * STRIDE + ky - 1;
            bool rv = (unsigned)iy < (unsigned)Hin;
            const float* rp = src + iy * Win;
            u64 vd[NIN];
#pragma unroll
            for (int j = 0; j < NIN; j++) {
                int ix = bx + j;
                float v = (rv && (unsigned)ix < (unsigned)Win) ? __ldg(rp + ix) : 0.0f;
                vd[j] = pack2(v, v);
            }
#pragma unroll
            for (int kx = 0; kx < 3; kx++) {
                const u64* wp = (const u64*)(ws + (ci * 9 + ky * 3 + kx) * COB);
#pragma unroll
                for (int cp = 0; cp < COB / 2; cp++) {
                    u64 w2 = wp[cp];
#pragma unroll
                    for (int p = 0; p < 4; p++)
                        ffma2(acc[cp][p], w2, vd[STRIDE * p + kx]);
                }
            }
        }
    }
}

template<int COB>
__device__ __forceinline__ void init_acc(u64 (&acc)[COB/2][4], const float* __restrict__ b, int co_base) {
#pragma unroll
    for (int cp = 0; cp < COB / 2; cp++) {
        u64 bb = pack2(__ldg(b + co_base + 2 * cp), __ldg(b + co_base + 2 * cp + 1));
#pragma unroll
        for (int p = 0; p < 4; p++) acc[cp][p] = bb;
    }
}

// ---------------- kernels ---------------------------------------------------
__global__ void zero_k(float* a, int n) {
    int i = blockIdx.x * blockDim.x + threadIdx.x;
    if (i < n) a[i] = 0.0f;
}

template<int CIN, int COB, int STRIDE, int CIU>
__global__ void __launch_bounds__(256) conv_relu_p4_k(
        const float* __restrict__ in, int cs,
        const float* __restrict__ w, const float* __restrict__ b,
        float* __restrict__ out, int Hin, int Win, int Hout, int Wout) {
    __shared__ float ws[CIN * 9 * COB];
    int co_base = blockIdx.y * COB;
    load_w_conv<CIN, COB>(ws, w, co_base);
    __syncthreads();
    int HWo = Hout * Wout;
    int px0 = (blockIdx.x * blockDim.x + threadIdx.x) * 4;
    if (px0 >= HWo) return;
    int y = px0 / Wout, x0 = px0 - y * Wout;
    u64 acc[COB/2][4];
    init_acc<COB>(acc, b, co_base);
    conv_p4<CIN, 0, COB, STRIDE, CIU>(acc, ws, in, cs, nullptr, 0, y, x0, Hin, Win);
#pragma unroll
    for (int cp = 0; cp < COB / 2; cp++) {
        float a0[4], a1[4];
#pragma unroll
        for (int p = 0; p < 4; p++) unpack2(acc[cp][p], a0[p], a1[p]);
        float4 v0 = make_float4(fmaxf(a0[0],0.f), fmaxf(a0[1],0.f), fmaxf(a0[2],0.f), fmaxf(a0[3],0.f));
        float4 v1 = make_float4(fmaxf(a1[0],0.f), fmaxf(a1[1],0.f), fmaxf(a1[2],0.f), fmaxf(a1[3],0.f));
        *(float4*)(out + (co_base + 2*cp    ) * HWo + px0) = v0;
        *(float4*)(out + (co_base + 2*cp + 1) * HWo + px0) = v1;
    }
}

// GRU gates: conv(cat(x,h)) -> 2*CH channels (sigmoid).
// co_base < CH  : r half -> rh = sigmoid(r)*h
// co_base >= CH : u half -> u
template<int CH, int CIU>
__global__ void __launch_bounds__(256) gru_gates_p4_k(
        const float* __restrict__ cx, const float* __restrict__ h,
        const float* __restrict__ wg, const float* __restrict__ bg,
        float* __restrict__ u_out, float* __restrict__ rh_out, int Hh, int Wh) {
    constexpr int COB = 8;
    __shared__ float ws[2 * CH * 9 * COB];
    int co_base = blockIdx.y * COB;
    load_w_conv<2 * CH, COB>(ws, wg, co_base);
    __syncthreads();
    int HW = Hh * Wh;
    int px0 = (blockIdx.x * blockDim.x + threadIdx.x) * 4;
    if (px0 >= HW) return;
    int y = px0 / Wh, x0 = px0 - y * Wh;
    u64 acc[COB/2][4];
    init_acc<COB>(acc, bg, co_base);
    conv_p4<CH, CH, COB, 1, CIU>(acc, ws, cx, HW, h, HW, y, x0, Hh, Wh);
    bool is_r = (co_base < CH);
#pragma unroll
    for (int cp = 0; cp < COB / 2; cp++) {
        float a0[4], a1[4];
#pragma unroll
        for (int p = 0; p < 4; p++) unpack2(acc[cp][p], a0[p], a1[p]);
        if (is_r) {
            int c0 = co_base + 2*cp, c1 = c0 + 1;
            float4 h0 = *(const float4*)(h + c0 * HW + px0);
            float4 h1 = *(const float4*)(h + c1 * HW + px0);
            float4 v0 = make_float4(sigf(a0[0])*h0.x, sigf(a0[1])*h0.y, sigf(a0[2])*h0.z, sigf(a0[3])*h0.w);
            float4 v1 = make_float4(sigf(a1[0])*h1.x, sigf(a1[1])*h1.y, sigf(a1[2])*h1.z, sigf(a1[3])*h1.w);
            *(float4*)(rh_out + c0 * HW + px0) = v0;
            *(float4*)(rh_out + c1 * HW + px0) = v1;
        } else {
            int c0 = co_base - CH + 2*cp, c1 = c0 + 1;
            float4 v0 = make_float4(sigf(a0[0]), sigf(a0[1]), sigf(a0[2]), sigf(a0[3]));
            float4 v1 = make_float4(sigf(a1[0]), sigf(a1[1]), sigf(a1[2]), sigf(a1[3]));
            *(float4*)(u_out + c0 * HW + px0) = v0;
            *(float4*)(u_out + c1 * HW + px0) = v1;
        }
    }
}

// GRU candidate: c = tanh(conv(cat(x, rh))); h = u*h + (1-u)*c (in place)
template<int CH, int CIU>
__global__ void __launch_bounds__(256) gru_cand_p4_k(
        const float* __restrict__ cx, const float* __restrict__ rh,
        const float* __restrict__ wc, const float* __restrict__ bc,
        const float* __restrict__ u, float* __restrict__ h, int Hh, int Wh) {
    constexpr int COB = 8;
    __shared__ float ws[2 * CH * 9 * COB];
    int co_base = blockIdx.y * COB;
    load_w_conv<2 * CH, COB>(ws, wc, co_base);
    __syncthreads();
    int HW = Hh * Wh;
    int px0 = (blockIdx.x * blockDim.x + threadIdx.x) * 4;
    if (px0 >= HW) return;
    int y = px0 / Wh, x0 = px0 - y * Wh;
    u64 acc[COB/2][4];
    init_acc<COB>(acc, bc, co_base);
    conv_p4<CH, CH, COB, 1, CIU>(acc, ws, cx, HW, rh, HW, y, x0, Hh, Wh);
#pragma unroll
    for (int cp = 0; cp < COB / 2; cp++) {
        float a0[4], a1[4];
#pragma unroll
        for (int p = 0; p < 4; p++) unpack2(acc[cp][p], a0[p], a1[p]);
        int c0 = co_base + 2*cp, c1 = c0 + 1;
        float4 u0 = *(const float4*)(u + c0 * HW + px0);
        float4 u1 = *(const float4*)(u + c1 * HW + px0);
        float4 h0 = *(const float4*)(h + c0 * HW + px0);
        float4 h1 = *(const float4*)(h + c1 * HW + px0);
        float4 o0, o1;
        o0.x = u0.x*h0.x + (1.f-u0.x)*tanh_fast(a0[0]);
        o0.y = u0.y*h0.y + (1.f-u0.y)*tanh_fast(a0[1]);
        o0.z = u0.z*h0.z + (1.f-u0.z)*tanh_fast(a0[2]);
        o0.w = u0.w*h0.w + (1.f-u0.w)*tanh_fast(a0[3]);
        o1.x = u1.x*h1.x + (1.f-u1.x)*tanh_fast(a1[0]);
        o1.y = u1.y*h1.y + (1.f-u1.y)*tanh_fast(a1[1]);
        o1.z = u1.z*h1.z + (1.f-u1.z)*tanh_fast(a1[2]);
        o1.w = u1.w*h1.w + (1.f-u1.w)*tanh_fast(a1[3]);
        *(float4*)(h + c0 * HW + px0) = o0;
        *(float4*)(h + c1 * HW + px0) = o1;
    }
}

// ConvTranspose2d(k=3,s=2,p=1,op=1) gather, P4 strip, fused add+relu.
// Output strip at even x0 (x0 % 4 == 0). Tap tables derived from parity.
template<int CIN, int COB, int COUT_TOT>
__global__ void __launch_bounds__(256) deconv_add_relu_p4_k(
        const float* __restrict__ in, const float* __restrict__ w,
        const float* __restrict__ b, const float* __restrict__ add,
        float* __restrict__ out, int Hin, int Win, int Hout, int Wout) {
    __shared__ float ws[CIN * 9 * COB];
    int co_base = blockIdx.y * COB;
    load_w_deconv<CIN, COB, COUT_TOT>(ws, w, co_base);
    __syncthreads();
    int HWi = Hin * Win, HWo = Hout * Wout;
    int px0 = (blockIdx.x * blockDim.x + threadIdx.x) * 4;
    if (px0 >= HWo) return;
    int y = px0 / Wout, x0 = px0 - y * Wout;
    int hx = x0 >> 1;
    u64 acc[COB/2][4];
    init_acc<COB>(acc, b, co_base);
    const int pA[3] = {1, 0, 1}, jA[3] = {1, 0, 0};
    const int pB[3] = {3, 2, 3}, jB[3] = {2, 1, 1};
#pragma unroll
    for (int ky = 0; ky < 3; ky++) {
        int t = y + 1 - ky;
        if (t < 0 || (t & 1)) continue;
        int iy = t >> 1;
        if (iy >= Hin) continue;
#pragma unroll 4
        for (int ci = 0; ci < CIN; ci++) {
            const float* rp = in + ci * HWi + iy * Win;
            u64 vd[3];
#pragma unroll
            for (int j = 0; j < 3; j++) {
                float v = (hx + j < Win) ? __ldg(rp + hx + j) : 0.0f;
                vd[j] = pack2(v, v);
            }
#pragma unroll
            for (int kx = 0; kx < 3; kx++) {
                const u64* wp = (const u64*)(ws + (ci * 9 + ky * 3 + kx) * COB);
#pragma unroll
                for (int cp = 0; cp < COB / 2; cp++) {
                    u64 w2 = wp[cp];
                    ffma2(acc[cp][pA[kx]], w2, vd[jA[kx]]);
                    ffma2(acc[cp][pB[kx]], w2, vd[jB[kx]]);
                }
            }
        }
    }
#pragma unroll
    for (int cp = 0; cp < COB / 2; cp++) {
        float a0[4], a1[4];
#pragma unroll
        for (int p = 0; p < 4; p++) unpack2(acc[cp][p], a0[p], a1[p]);
        int c0 = co_base + 2*cp, c1 = c0 + 1;
        float4 s0 = *(const float4*)(add + c0 * HWo + px0);
        float4 s1 = *(const float4*)(add + c1 * HWo + px0);
        float4 v0 = make_float4(fmaxf(a0[0]+s0.x,0.f), fmaxf(a0[1]+s0.y,0.f),
                                fmaxf(a0[2]+s0.z,0.f), fmaxf(a0[3]+s0.w,0.f));
        float4 v1 = make_float4(fmaxf(a1[0]+s1.x,0.f), fmaxf(a1[1]+s1.y,0.f),
                                fmaxf(a1[2]+s1.z,0.f), fmaxf(a1[3]+s1.w,0.f));
        *(float4*)(out + c0 * HWo + px0) = v0;
        *(float4*)(out + c1 * HWo + px0) = v1;
    }
}

// Final deconv to 1 channel, P4 strip, scalar accumulation (tiny FLOPs).
template<int CIN>
__global__ void __launch_bounds__(256) deconv_out_p4_k(
        const float* __restrict__ in, const float* __restrict__ w,
        const float* __restrict__ b, float* __restrict__ out,
        int Hin, int Win, int Hout, int Wout) {
    __shared__ float ws[CIN * 9];
    for (int i = threadIdx.x; i < CIN * 9; i += blockDim.x) ws[i] = w[i]; // cout=1
    __syncthreads();
    int HWi = Hin * Win, HWo = Hout * Wout;
    int px0 = (blockIdx.x * blockDim.x + threadIdx.x) * 4;
    if (px0 >= HWo) return;
    int y = px0 / Wout, x0 = px0 - y * Wout;
    int hx = x0 >> 1;
    float bias = __ldg(b);
    float acc[4] = {bias, bias, bias, bias};
#pragma unroll
    for (int ky = 0; ky < 3; ky++) {
        int t = y + 1 - ky;
        if (t < 0 || (t & 1)) continue;
        int iy = t >> 1;
        if (iy >= Hin) continue;
#pragma unroll
        for (int ci = 0; ci < CIN; ci++) {
            const float* rp = in + ci * HWi + iy * Win;
            float r0 = __ldg(rp + hx);
            float r1 = (hx + 1 < Win) ? __ldg(rp + hx + 1) : 0.0f;
            float r2 = (hx + 2 < Win) ? __ldg(rp + hx + 2) : 0.0f;
            float w0 = ws[ci*9 + ky*3 + 0];
            float w1 = ws[ci*9 + ky*3 + 1];
            float w2 = ws[ci*9 + ky*3 + 2];
            acc[0] = fmaf(w1, r0, acc[0]);
            acc[1] = fmaf(w0, r1, fmaf(w2, r0, acc[1]));
            acc[2] = fmaf(w1, r1, acc[2]);
            acc[3] = fmaf(w0, r2, fmaf(w2, r1, acc[3]));
        }
    }
    *(float4*)(out + px0) = make_float4(acc[0], acc[1], acc[2], acc[3]);
}

// ---------------- launch ----------------------------------------------------
extern "C" void kernel_launch(void* const* d_in, const int* in_sizes, int n_in,
                              void* d_out, int out_size) {
    const float* vol  = (const float*)d_in[0];
    const float* c1w  = (const float*)d_in[1];
    const float* c1b  = (const float*)d_in[2];
    const float* g1wg = (const float*)d_in[3];
    const float* g1bg = (const float*)d_in[4];
    const float* g1wc = (const float*)d_in[5];
    const float* g1bc = (const float*)d_in[6];
    const float* c2w  = (const float*)d_in[7];
    const float* c2b  = (const float*)d_in[8];
    const float* g2wg = (const float*)d_in[9];
    const float* g2bg = (const float*)d_in[10];
    const float* g2wc = (const float*)d_in[11];
    const float* g2bc = (const float*)d_in[12];
    const float* u1w  = (const float*)d_in[13];
    const float* u1b  = (const float*)d_in[14];
    const float* u2w  = (const float*)d_in[15];
    const float* u2b  = (const float*)d_in[16];
    float* out = (float*)d_out;

    float *s1, *s2, *c1, *u1, *rh1, *c2, *u2, *rh2, *up;
    cudaGetSymbolAddress((void**)&s1,  g_s1);
    cudaGetSymbolAddress((void**)&s2,  g_s2);
    cudaGetSymbolAddress((void**)&c1,  g_c1);
    cudaGetSymbolAddress((void**)&u1,  g_u1);
    cudaGetSymbolAddress((void**)&rh1, g_rh1);
    cudaGetSymbolAddress((void**)&c2,  g_c2);
    cudaGetSymbolAddress((void**)&u2,  g_u2);
    cudaGetSymbolAddress((void**)&rh2, g_rh2);
    cudaGetSymbolAddress((void**)&up,  g_up);

    const int TB = 256;
    zero_k<<<(8 * HW1 + TB - 1) / TB, TB>>>(s1, 8 * HW1);
    zero_k<<<(16 * HW2 + TB - 1) / TB, TB>>>(s2, 16 * HW2);

    int nb1 = HW1 / (TB * 4);   // 80
    int nb2 = HW2 / (TB * 4);   // 20
    int nbo = HWO / (TB * 4);   // 320

    for (int d = 0; d < DEPTH; d++) {
        // c1 = relu(conv1(cost_d))
        conv_relu_p4_k<32, 8, 1, 4><<<dim3(nb1, 1), TB>>>(vol + (long)d * HW1, DEPTH * HW1,
                                                          c1w, c1b, c1, H1, W1, H1, W1);
        // s1 = GRU1(c1, s1)
        gru_gates_p4_k<8, 4><<<dim3(nb1, 2), TB>>>(c1, s1, g1wg, g1bg, u1, rh1, H1, W1);
        gru_cand_p4_k<8, 4><<<dim3(nb1, 1), TB>>>(c1, rh1, g1wc, g1bc, u1, s1, H1, W1);
        // c2 = relu(conv2(s1)) stride 2
        conv_relu_p4_k<8, 8, 2, 4><<<dim3(nb2, 2), TB>>>(s1, HW1, c2w, c2b, c2, H1, W1, H2, W2);
        // s2 = GRU2(c2, s2)
        gru_gates_p4_k<16, 4><<<dim3(nb2, 4), TB>>>(c2, s2, g2wg, g2bg, u2, rh2, H2, W2);
        gru_cand_p4_k<16, 4><<<dim3(nb2, 2), TB>>>(c2, rh2, g2wc, g2bc, u2, s2, H2, W2);
        // up = relu(deconv(s2) + s1)
        deconv_add_relu_p4_k<16, 8, 8><<<dim3(nb1, 1), TB>>>(s2, u1w, u1b, s1, up, H2, W2, H1, W1);
        // out_d = deconv(up)
        deconv_out_p4_k<8><<<dim3(nbo, 1), TB>>>(up, u2w, u2b, out + (long)d * HWO,
                                                 H1, W1, HOUT, WOUT);
    }
}